// round 13
// baseline (speedup 1.0000x reference)
#include <cuda_runtime.h>
#include <math_constants.h>

// Problem constants (fixed by the dataset: B=32, N=2048)
#define BATCH 32
#define NPTS  2048
#define TPB   256
#define NWARP (TPB / 32)           // 8 warps per block
#define CPB   32                   // chunks per batch
#define ROWS  64                   // rows per unit
#define NUNITS (BATCH * CPB)       // 1024 work units
#define GRIDP 304                  // persistent blocks (~2 per SM)
#define MRW   (NPTS / NWARP)       // m-range per warp = 256
#define GPW   (MRW / 4)            // 64 groups of 4 points per warp

__device__ double g_partial[NUNITS];
__device__ unsigned int g_ticket = 0;
__device__ unsigned int g_done = 0;

typedef unsigned long long u64;

__device__ __forceinline__ u64 pack2(float lo, float hi) {
    u64 r;
    asm("mov.b64 %0, {%1, %2};" : "=l"(r) : "f"(lo), "f"(hi));
    return r;
}
__device__ __forceinline__ void unpack2(u64 v, float& lo, float& hi) {
    asm("mov.b64 {%0, %1}, %2;" : "=f"(lo), "=f"(hi) : "l"(v));
}
__device__ __forceinline__ u64 ffma2(u64 a, u64 b, u64 c) {
    u64 d;
    asm("fma.rn.f32x2 %0, %1, %2, %3;" : "=l"(d) : "l"(a), "l"(b), "l"(c));
    return d;
}

__device__ __forceinline__ void quat2mat(const float* __restrict__ q, float* R) {
    float w = q[0], x = q[1], y = q[2], z = q[3];
    float inv = 1.0f / sqrtf(w * w + x * x + y * y + z * z);
    w *= inv; x *= inv; y *= inv; z *= inv;
    R[0] = 1.f - 2.f * (y * y + z * z); R[1] = 2.f * (x * y - w * z); R[2] = 2.f * (x * z + w * y);
    R[3] = 2.f * (x * y + w * z);       R[4] = 1.f - 2.f * (x * x + z * z); R[5] = 2.f * (y * z - w * x);
    R[6] = 2.f * (x * z - w * y);       R[7] = 2.f * (y * z + w * x);       R[8] = 1.f - 2.f * (x * x + y * y);
}

__global__ void __launch_bounds__(TPB)
pts_loss_kernel(const float* __restrict__ q_est,
                const float* __restrict__ q_gt,
                const float* __restrict__ pts,
                const int*   __restrict__ sym,
                float* __restrict__ out)
{
    const int tid = threadIdx.x;
    const int wid = tid >> 5;
    const int lid = tid & 31;

    // Interleaved SoA table: group g of 4 points -> 64 contiguous bytes
    // [x0..x3][y0..y3][z0..z3][w0..w3]; one LDS.128 per component quad.
    __shared__ __align__(16) float s_tab[NPTS * 4];   // 32 KB
    __shared__ float s_min[NWARP][ROWS];
    __shared__ float s_xx[ROWS];
    __shared__ float red[2];
    __shared__ int   s_t;

    int cur_b = -1;   // batch whose rotations are loaded
    int tab_b = -1;   // batch whose y-table is resident in smem
    float Re[9], Rg[9];

    for (;;) {
        if (tid == 0) s_t = (int)atomicAdd(&g_ticket, 1u);
        __syncthreads();
        const int t = s_t;
        if (t >= NUNITS) break;

        const int b     = t >> 5;      // batch-major tickets -> table reuse
        const int chunk = t & 31;

        if (b != cur_b) {
            cur_b = b;
            quat2mat(q_est + 4 * b, Re);
            quat2mat(q_gt  + 4 * b, Rg);
        }
        const float* __restrict__ P = pts + (size_t)b * NPTS * 3;
        const bool is_sym = (sym[b] != 0);

        float local = 0.0f;

        if (!is_sym) {
            // d_p: rows chunk*64 .. +64 on threads 0..63
            if (tid < ROWS) {
                float D[9];
                #pragma unroll
                for (int i = 0; i < 9; i++) D[i] = Re[i] - Rg[i];
                const int n = chunk * ROWS + tid;
                const float p0 = P[3 * n], p1 = P[3 * n + 1], p2 = P[3 * n + 2];
                const float e0 = D[0] * p0 + D[1] * p1 + D[2] * p2;
                const float e1 = D[3] * p0 + D[4] * p1 + D[5] * p2;
                const float e2 = D[6] * p0 + D[7] * p1 + D[8] * p2;
                local = e0 * e0 + e1 * e1 + e2 * e2;
            }
        } else {
            if (tab_b != b) {
                // Build interleaved y-table: (-2*y0, -2*y1, -2*y2, yy)
                for (int m = tid; m < NPTS; m += TPB) {
                    const float p0 = P[3 * m], p1 = P[3 * m + 1], p2 = P[3 * m + 2];
                    const float y0 = Rg[0] * p0 + Rg[1] * p1 + Rg[2] * p2;
                    const float y1 = Rg[3] * p0 + Rg[4] * p1 + Rg[5] * p2;
                    const float y2 = Rg[6] * p0 + Rg[7] * p1 + Rg[8] * p2;
                    const int g = m >> 2, j = m & 3;
                    float* tt = s_tab + g * 16;
                    tt[j]      = -2.f * y0;
                    tt[j + 4]  = -2.f * y1;
                    tt[j + 8]  = -2.f * y2;
                    tt[j + 12] = y0 * y0 + y1 * y1 + y2 * y2;
                }
                tab_b = b;
                __syncthreads();
            }

            // Lane lid owns rows lid, lid+32; warp scans its m-eighth.
            u64 XA0, XA1, XA2, XB0, XB1, XB2;
            {
                const int n = chunk * ROWS + lid;
                const float p0 = P[3 * n], p1 = P[3 * n + 1], p2 = P[3 * n + 2];
                const float x0 = Re[0] * p0 + Re[1] * p1 + Re[2] * p2;
                const float x1 = Re[3] * p0 + Re[4] * p1 + Re[5] * p2;
                const float x2 = Re[6] * p0 + Re[7] * p1 + Re[8] * p2;
                XA0 = pack2(x0, x0); XA1 = pack2(x1, x1); XA2 = pack2(x2, x2);
                if (wid == 0) s_xx[lid] = x0 * x0 + x1 * x1 + x2 * x2;
            }
            {
                const int n = chunk * ROWS + lid + 32;
                const float p0 = P[3 * n], p1 = P[3 * n + 1], p2 = P[3 * n + 2];
                const float x0 = Re[0] * p0 + Re[1] * p1 + Re[2] * p2;
                const float x1 = Re[3] * p0 + Re[4] * p1 + Re[5] * p2;
                const float x2 = Re[6] * p0 + Re[7] * p1 + Re[8] * p2;
                XB0 = pack2(x0, x0); XB1 = pack2(x1, x1); XB2 = pack2(x2, x2);
                if (wid == 0) s_xx[lid + 32] = x0 * x0 + x1 * x1 + x2 * x2;
            }

            float mA0 = CUDART_INF_F, mA1 = CUDART_INF_F, mA2 = CUDART_INF_F, mA3 = CUDART_INF_F;
            float mB0 = CUDART_INF_F, mB1 = CUDART_INF_F, mB2 = CUDART_INF_F, mB3 = CUDART_INF_F;

            const float* __restrict__ base = s_tab + wid * (GPW * 16);

            #pragma unroll 2
            for (int g = 0; g < GPW; g += 2) {
                const ulonglong2* __restrict__ q0 = (const ulonglong2*)(base + g * 16);
                const ulonglong2* __restrict__ q1 = (const ulonglong2*)(base + g * 16 + 16);
                const ulonglong2 vx0 = q0[0], vy0 = q0[1], vz0 = q0[2], vw0 = q0[3];
                const ulonglong2 vx1 = q1[0], vy1 = q1[1], vz1 = q1[2], vw1 = q1[3];

                float a, c, d, e;
                unpack2(ffma2(vx0.x, XA0, ffma2(vy0.x, XA1, ffma2(vz0.x, XA2, vw0.x))), a, c);
                unpack2(ffma2(vx0.y, XA0, ffma2(vy0.y, XA1, ffma2(vz0.y, XA2, vw0.y))), d, e);
                mA0 = fminf(mA0, a); mA1 = fminf(mA1, c); mA2 = fminf(mA2, d); mA3 = fminf(mA3, e);
                unpack2(ffma2(vx0.x, XB0, ffma2(vy0.x, XB1, ffma2(vz0.x, XB2, vw0.x))), a, c);
                unpack2(ffma2(vx0.y, XB0, ffma2(vy0.y, XB1, ffma2(vz0.y, XB2, vw0.y))), d, e);
                mB0 = fminf(mB0, a); mB1 = fminf(mB1, c); mB2 = fminf(mB2, d); mB3 = fminf(mB3, e);
                unpack2(ffma2(vx1.x, XA0, ffma2(vy1.x, XA1, ffma2(vz1.x, XA2, vw1.x))), a, c);
                unpack2(ffma2(vx1.y, XA0, ffma2(vy1.y, XA1, ffma2(vz1.y, XA2, vw1.y))), d, e);
                mA0 = fminf(mA0, a); mA1 = fminf(mA1, c); mA2 = fminf(mA2, d); mA3 = fminf(mA3, e);
                unpack2(ffma2(vx1.x, XB0, ffma2(vy1.x, XB1, ffma2(vz1.x, XB2, vw1.x))), a, c);
                unpack2(ffma2(vx1.y, XB0, ffma2(vy1.y, XB1, ffma2(vz1.y, XB2, vw1.y))), d, e);
                mB0 = fminf(mB0, a); mB1 = fminf(mB1, c); mB2 = fminf(mB2, d); mB3 = fminf(mB3, e);
            }

            s_min[wid][lid]      = fminf(fminf(mA0, mA1), fminf(mA2, mA3));
            s_min[wid][lid + 32] = fminf(fminf(mB0, mB1), fminf(mB2, mB3));
            __syncthreads();

            if (tid < ROWS) {
                float mm = s_min[0][tid];
                #pragma unroll
                for (int w = 1; w < NWARP; w++) mm = fminf(mm, s_min[w][tid]);
                local = s_xx[tid] + mm;
            }
        }

        // Per-unit deterministic reduction: local nonzero only in warps 0,1.
        if (wid < 2) {
            float v = local;
            #pragma unroll
            for (int off = 16; off > 0; off >>= 1)
                v += __shfl_down_sync(0xffffffffu, v, off);
            if (lid == 0) red[wid] = v;
        }
        __syncthreads();
        if (tid == 0) g_partial[t] = (double)(red[0] + red[1]);
        __syncthreads();   // protect red/s_t/s_min reuse next unit
    }

    // Finalize: last persistent block reduces all unit partials (fixed order).
    __shared__ bool is_last;
    __shared__ double sd[TPB];
    if (tid == 0) {
        __threadfence();
        unsigned int c = atomicAdd(&g_done, 1u);
        is_last = (c == GRIDP - 1);
    }
    __syncthreads();

    if (is_last) {
        double acc = 0.0;
        #pragma unroll
        for (int i = 0; i < NUNITS / TPB; i++)
            acc += g_partial[tid + i * TPB];
        sd[tid] = acc;
        __syncthreads();
        #pragma unroll
        for (int s = TPB / 2; s > 0; s >>= 1) {
            if (tid < s) sd[tid] += sd[tid + s];
            __syncthreads();
        }
        if (tid == 0) {
            out[0] = (float)(sd[0] / (2.0 * (double)NPTS * (double)BATCH));
            g_ticket = 0;     // reset for next (graph-replayed) call
            g_done   = 0;
        }
    }
}

extern "C" void kernel_launch(void* const* d_in, const int* in_sizes, int n_in,
                              void* d_out, int out_size)
{
    // metadata order: q_est(32x4), q_gt(32x4), T(32x3, unused), pts(32x2048x3), symmetries(32x1 int32)
    const float* q_est = (const float*)d_in[0];
    const float* q_gt  = (const float*)d_in[1];
    const float* pts   = (const float*)d_in[3];
    const int*   sym   = (const int*)d_in[4];
    float* out = (float*)d_out;

    pts_loss_kernel<<<GRIDP, TPB>>>(q_est, q_gt, pts, sym, out);
}

// round 14
// speedup vs baseline: 1.1315x; 1.1315x over previous
#include <cuda_runtime.h>
#include <math_constants.h>

// Problem constants (fixed by the dataset: B=32, N=2048)
#define BATCH 32
#define NPTS  2048
#define TPB   256
#define NWARP (TPB / 32)           // 8 warps per block
#define ROWS  128                  // rows per block (RPL=4)
#define RPL   4
#define CHUNKS 16                  // row-chunks per batch
#define MPTS  1024                 // points per m-half
#define GRID  (BATCH * CHUNKS * 2) // 1024 blocks
#define PAIRS (BATCH * CHUNKS)     // 512 (batch,chunk) units
#define LGRP  (MPTS / 4)           // 256 local groups per block
#define GPW   (LGRP / NWARP)       // 32 groups per warp

__device__ float  g_rowmin[2][PAIRS][ROWS];
__device__ double g_partial[PAIRS];
__device__ int    g_pairdone[PAIRS];
__device__ unsigned int g_done = 0;

typedef unsigned long long u64;

__device__ __forceinline__ u64 pack2(float lo, float hi) {
    u64 r;
    asm("mov.b64 %0, {%1, %2};" : "=l"(r) : "f"(lo), "f"(hi));
    return r;
}
__device__ __forceinline__ void unpack2(u64 v, float& lo, float& hi) {
    asm("mov.b64 {%0, %1}, %2;" : "=f"(lo), "=f"(hi) : "l"(v));
}
__device__ __forceinline__ u64 ffma2(u64 a, u64 b, u64 c) {
    u64 d;
    asm("fma.rn.f32x2 %0, %1, %2, %3;" : "=l"(d) : "l"(a), "l"(b), "l"(c));
    return d;
}

__device__ __forceinline__ void quat2mat(const float* __restrict__ q, float* R) {
    float w = q[0], x = q[1], y = q[2], z = q[3];
    float inv = 1.0f / sqrtf(w * w + x * x + y * y + z * z);
    w *= inv; x *= inv; y *= inv; z *= inv;
    R[0] = 1.f - 2.f * (y * y + z * z); R[1] = 2.f * (x * y - w * z); R[2] = 2.f * (x * z + w * y);
    R[3] = 2.f * (x * y + w * z);       R[4] = 1.f - 2.f * (x * x + z * z); R[5] = 2.f * (y * z - w * x);
    R[6] = 2.f * (x * z - w * y);       R[7] = 2.f * (y * z + w * x);       R[8] = 1.f - 2.f * (x * x + y * y);
}

__global__ void __launch_bounds__(TPB, 3)
pts_loss_kernel(const float* __restrict__ q_est,
                const float* __restrict__ q_gt,
                const float* __restrict__ pts,
                const int*   __restrict__ sym,
                float* __restrict__ out)
{
    const int bid   = blockIdx.x;
    const int b     = bid & 31;            // interleaved batch
    const int r2    = bid >> 5;
    const int chunk = r2 & (CHUNKS - 1);
    const int mhalf = r2 >> 4;
    const int pidx  = bid & (PAIRS - 1);   // (batch, chunk) pair id
    const int tid   = threadIdx.x;
    const int wid   = tid >> 5;
    const int lid   = tid & 31;

    // Interleaved table for this m-half: group g (4 pts) -> 64 bytes
    __shared__ __align__(16) float s_tab[MPTS * 4];      // 16 KB
    __shared__ float s_min[NWARP][ROWS];                 // 4 KB
    __shared__ float s_xx[ROWS];
    __shared__ float s_red[NWARP];
    __shared__ bool  s_second;

    float Re[9], Rg[9];
    quat2mat(q_est + 4 * b, Re);
    quat2mat(q_gt  + 4 * b, Rg);

    const float* __restrict__ P = pts + (size_t)b * NPTS * 3;
    const bool is_sym = (sym[b] != 0);

    if (!is_sym) {
        // d_p handled only by the mhalf==0 block of the pair.
        if (mhalf == 0) {
            float local = 0.0f;
            if (tid < ROWS) {
                float D[9];
                #pragma unroll
                for (int i = 0; i < 9; i++) D[i] = Re[i] - Rg[i];
                const int n = chunk * ROWS + tid;
                const float p0 = P[3 * n], p1 = P[3 * n + 1], p2 = P[3 * n + 2];
                const float e0 = D[0] * p0 + D[1] * p1 + D[2] * p2;
                const float e1 = D[3] * p0 + D[4] * p1 + D[5] * p2;
                const float e2 = D[6] * p0 + D[7] * p1 + D[8] * p2;
                local = e0 * e0 + e1 * e1 + e2 * e2;
            }
            // warp reduce (warps 0-3 hold data)
            float v = local;
            #pragma unroll
            for (int off = 16; off > 0; off >>= 1)
                v += __shfl_down_sync(0xffffffffu, v, off);
            if (lid == 0) s_red[wid] = v;
            __syncthreads();
            if (tid == 0)
                g_partial[pidx] = (double)(((s_red[0] + s_red[1]) + (s_red[2] + s_red[3])) +
                                           ((s_red[4] + s_red[5]) + (s_red[6] + s_red[7])));
        }
    } else {
        // ---- Build table for points [mhalf*1024, mhalf*1024+1024) ----
        const int mbase = mhalf * MPTS;
        for (int i = tid; i < MPTS; i += TPB) {
            const int m = mbase + i;
            const float p0 = P[3 * m], p1 = P[3 * m + 1], p2 = P[3 * m + 2];
            const float y0 = Rg[0] * p0 + Rg[1] * p1 + Rg[2] * p2;
            const float y1 = Rg[3] * p0 + Rg[4] * p1 + Rg[5] * p2;
            const float y2 = Rg[6] * p0 + Rg[7] * p1 + Rg[8] * p2;
            const int g = i >> 2, j = i & 3;
            float* t = s_tab + g * 16;
            t[j]      = -2.f * y0;
            t[j + 4]  = -2.f * y1;
            t[j + 8]  = -2.f * y2;
            t[j + 12] = y0 * y0 + y1 * y1 + y2 * y2;
        }
        __syncthreads();

        // ---- Per-lane rows (RPL=4): n = chunk*128 + lid + 32*r ----
        u64 X0[RPL], X1[RPL], X2[RPL];
        #pragma unroll
        for (int r = 0; r < RPL; r++) {
            const int n = chunk * ROWS + lid + 32 * r;
            const float p0 = P[3 * n], p1 = P[3 * n + 1], p2 = P[3 * n + 2];
            const float x0 = Re[0] * p0 + Re[1] * p1 + Re[2] * p2;
            const float x1 = Re[3] * p0 + Re[4] * p1 + Re[5] * p2;
            const float x2 = Re[6] * p0 + Re[7] * p1 + Re[8] * p2;
            X0[r] = pack2(x0, x0);
            X1[r] = pack2(x1, x1);
            X2[r] = pack2(x2, x2);
            if (wid == 0) s_xx[lid + 32 * r] = x0 * x0 + x1 * x1 + x2 * x2;
        }

        float mn[RPL][2];
        #pragma unroll
        for (int r = 0; r < RPL; r++) { mn[r][0] = CUDART_INF_F; mn[r][1] = CUDART_INF_F; }

        const float* __restrict__ base = s_tab + wid * (GPW * 16);

        // ---- Scan this warp's 32 groups (128 points) for 128 rows ----
        #pragma unroll 2
        for (int g = 0; g < GPW; g += 2) {
            const ulonglong2* __restrict__ q0 = (const ulonglong2*)(base + g * 16);
            const ulonglong2* __restrict__ q1 = (const ulonglong2*)(base + g * 16 + 16);
            const ulonglong2 vx0 = q0[0], vy0 = q0[1], vz0 = q0[2], vw0 = q0[3];
            const ulonglong2 vx1 = q1[0], vy1 = q1[1], vz1 = q1[2], vw1 = q1[3];

            #pragma unroll
            for (int r = 0; r < RPL; r++) {
                float a0, a1, b0, b1, c0, c1, d0, d1;
                unpack2(ffma2(vx0.x, X0[r], ffma2(vy0.x, X1[r], ffma2(vz0.x, X2[r], vw0.x))), a0, a1);
                unpack2(ffma2(vx0.y, X0[r], ffma2(vy0.y, X1[r], ffma2(vz0.y, X2[r], vw0.y))), b0, b1);
                unpack2(ffma2(vx1.x, X0[r], ffma2(vy1.x, X1[r], ffma2(vz1.x, X2[r], vw1.x))), c0, c1);
                unpack2(ffma2(vx1.y, X0[r], ffma2(vy1.y, X1[r], ffma2(vz1.y, X2[r], vw1.y))), d0, d1);
                mn[r][0] = fminf(fminf(mn[r][0], a0), fminf(a1, b0));
                mn[r][1] = fminf(fminf(mn[r][1], b1), fminf(c0, c1));
                mn[r][0] = fminf(mn[r][0], d0);
                mn[r][1] = fminf(mn[r][1], d1);
            }
        }

        #pragma unroll
        for (int r = 0; r < RPL; r++)
            s_min[wid][lid + 32 * r] = fminf(mn[r][0], mn[r][1]);
        __syncthreads();

        // Combine 8 warps -> per-row min; publish to global
        if (tid < ROWS) {
            float mm = s_min[0][tid];
            #pragma unroll
            for (int w = 1; w < NWARP; w++) mm = fminf(mm, s_min[w][tid]);
            g_rowmin[mhalf][pidx][tid] = mm;
        }
        __syncthreads();

        // Pair handshake: second arriving block combines both halves.
        if (tid == 0) {
            __threadfence();
            s_second = (atomicAdd(&g_pairdone[pidx], 1) == 1);
        }
        __syncthreads();

        if (s_second) {
            __threadfence();   // see partner's g_rowmin
            float local = 0.0f;
            if (tid < ROWS) {
                const float m0 = g_rowmin[0][pidx][tid];
                const float m1 = g_rowmin[1][pidx][tid];
                local = s_xx[tid] + fminf(m0, m1);
            }
            float v = local;
            #pragma unroll
            for (int off = 16; off > 0; off >>= 1)
                v += __shfl_down_sync(0xffffffffu, v, off);
            if (lid == 0) s_red[wid] = v;
            __syncthreads();
            if (tid == 0) {
                g_partial[pidx] = (double)(((s_red[0] + s_red[1]) + (s_red[2] + s_red[3])) +
                                           ((s_red[4] + s_red[5]) + (s_red[6] + s_red[7])));
                g_pairdone[pidx] = 0;      // reset for next replay
            }
        }
    }

    // ---- Finalize: last of all 1024 blocks sums the 512 pair partials ----
    __shared__ bool is_last;
    __shared__ double sd[TPB];
    if (tid == 0) {
        __threadfence();
        is_last = (atomicAdd(&g_done, 1u) == GRID - 1);
    }
    __syncthreads();

    if (is_last) {
        double acc = 0.0;
        #pragma unroll
        for (int i = 0; i < PAIRS / TPB; i++)
            acc += g_partial[tid + i * TPB];
        sd[tid] = acc;
        __syncthreads();
        #pragma unroll
        for (int s = TPB / 2; s > 0; s >>= 1) {
            if (tid < s) sd[tid] += sd[tid + s];
            __syncthreads();
        }
        if (tid == 0) {
            out[0] = (float)(sd[0] / (2.0 * (double)NPTS * (double)BATCH));
            g_done = 0;   // reset for next (graph-replayed) call
        }
    }
}

extern "C" void kernel_launch(void* const* d_in, const int* in_sizes, int n_in,
                              void* d_out, int out_size)
{
    // metadata order: q_est(32x4), q_gt(32x4), T(32x3, unused), pts(32x2048x3), symmetries(32x1 int32)
    const float* q_est = (const float*)d_in[0];
    const float* q_gt  = (const float*)d_in[1];
    const float* pts   = (const float*)d_in[3];
    const int*   sym   = (const int*)d_in[4];
    float* out = (float*)d_out;

    pts_loss_kernel<<<GRID, TPB>>>(q_est, q_gt, pts, sym, out);
}